// round 11
// baseline (speedup 1.0000x reference)
#include <cuda_runtime.h>
#include <cuda_fp16.h>
#include <math.h>
#include <stdint.h>

#define BATCH 25
#define SEQT  600
#define EMBD  300
#define HID   512
#define G3    1536              // 3*HID
#define MROWS (BATCH*SEQT)      // 15000
#define KP    304               // padded K for input GEMM (19 x 16)

#define WSTR  520               // smem fp16 row stride (conflict-free)
#define HROWS 26                // 25 batches + 1 zero row

// ---------------- scratch (device globals; no allocation allowed) ----------
__device__ float g_xg[(size_t)MROWS * G3];   // xg0 (layer-0 input gates)
__device__ __half g_ahi[(size_t)MROWS * KP]; // emb-gathered A, fp16 hi
__device__ __half g_alo[(size_t)MROWS * KP]; // fp16 lo (residual)
__device__ __half g_whi[(size_t)G3 * KP];    // w_ih0 fp16 hi
__device__ __half g_wlo[(size_t)G3 * KP];    // w_ih0 fp16 lo
__device__ __half g_h0[2][BATCH * HID];      // fp16 h transport (|h|<1)
__device__ __half g_h1[2][BATCH * HID];
__device__ float g_h0f[BATCH * HID];
__device__ float g_h1f[BATCH * HID];
__device__ unsigned g_ctr;                   // monotonic barrier counter
__device__ unsigned g_done;                  // completion counter (self-reset)

// ---------------- ptx helpers ----------------------------------------------
__device__ __forceinline__ void red_release_add(unsigned* p, unsigned v) {
    asm volatile("red.release.gpu.global.add.u32 [%0], %1;"
                 :: "l"(p), "r"(v) : "memory");
}
__device__ __forceinline__ unsigned ld_relaxed(const unsigned* p) {
    unsigned v;
    asm volatile("ld.relaxed.gpu.global.u32 %0, [%1];"
                 : "=r"(v) : "l"(p) : "memory");
    return v;
}
__device__ __forceinline__ uint32_t smem_u32(const void* p) {
    uint32_t a;
    asm("{ .reg .u64 t; cvta.to.shared.u64 t, %1; cvt.u32.u64 %0, t; }"
        : "=r"(a) : "l"(p));
    return a;
}
__device__ __forceinline__ void ldm_x4(uint32_t* r, uint32_t addr) {
    asm volatile("ldmatrix.sync.aligned.m8n8.x4.shared.b16 {%0,%1,%2,%3}, [%4];"
                 : "=r"(r[0]), "=r"(r[1]), "=r"(r[2]), "=r"(r[3])
                 : "r"(addr));
}
__device__ __forceinline__ void mma_fp16(float* d, const uint32_t* a,
                                         uint32_t b0, uint32_t b1) {
    asm volatile(
        "mma.sync.aligned.m16n8k16.row.col.f32.f16.f16.f32 "
        "{%0,%1,%2,%3}, {%4,%5,%6,%7}, {%8,%9}, {%0,%1,%2,%3};"
        : "+f"(d[0]), "+f"(d[1]), "+f"(d[2]), "+f"(d[3])
        : "r"(a[0]), "r"(a[1]), "r"(a[2]), "r"(a[3]), "r"(b0), "r"(b1));
}
__device__ __forceinline__ void cp_async4(uint32_t saddr, const void* g) {
    asm volatile("cp.async.ca.shared.global [%0], [%1], 4;"
                 :: "r"(saddr), "l"(g) : "memory");
}
__device__ __forceinline__ uint32_t pack_h2(float x, float y) {
    __half2 h = __halves2half2(__float2half_rn(x), __float2half_rn(y));
    return *(uint32_t*)&h;
}
__device__ __forceinline__ float fast_sig(float x) {
    return __fdividef(1.f, 1.f + __expf(-x));
}
__device__ __forceinline__ float fast_tanh(float x) {
    return 1.f - __fdividef(2.f, __expf(2.f * x) + 1.f);
}

// ---------------- convert kernels: fp32 -> fp16 hi/lo (padded K) ------------
__global__ void cvtA_kernel(const int* __restrict__ words,
                            const float* __restrict__ emb)
{
    const int row = blockIdx.x;
    const int k   = threadIdx.x;
    const int w   = words[row];
    const float v = (k < EMBD) ? emb[(size_t)w * EMBD + k] : 0.f;
    const __half h = __float2half_rn(v);
    g_ahi[(size_t)row * KP + k] = h;
    g_alo[(size_t)row * KP + k] = __float2half_rn(v - __half2float(h));
}

__global__ void cvtW_kernel(const float* __restrict__ w_ih0)
{
    const int row = blockIdx.x;
    const int k   = threadIdx.x;
    const float v = (k < EMBD) ? w_ih0[(size_t)row * EMBD + k] : 0.f;
    const __half h = __float2half_rn(v);
    g_whi[(size_t)row * KP + k] = h;
    g_wlo[(size_t)row * KP + k] = __float2half_rn(v - __half2float(h));
}

// ---------------- tensor-core input GEMM (fp16 hi/lo, 3 terms) --------------
#define ASTR 24
__global__ __launch_bounds__(256) void gemm_tc_kernel(
    const float* __restrict__ bias)
{
    __shared__ __half sah[128 * ASTR], sal[128 * ASTR];
    __shared__ __half swh[128 * ASTR], swl[128 * ASTR];

    const int tid  = threadIdx.x;
    const int wid  = tid >> 5;
    const int lane = tid & 31;
    const int m0   = blockIdx.y * 128;
    const int n0   = blockIdx.x * 128;
    const int mw   = wid & 3;
    const int nw   = wid >> 2;

    uint32_t abh[2], abl[2];
    {
        const int t = lane >> 3, ir = lane & 7;
        const int ac = (t >> 1) * 8;
#pragma unroll
        for (int mt = 0; mt < 2; mt++) {
            const int ar = mw * 32 + mt * 16 + (t & 1) * 8 + ir;
            const uint32_t off = (uint32_t)(ar * ASTR + ac) * 2u;
            abh[mt] = smem_u32(sah) + off;
            abl[mt] = smem_u32(sal) + off;
        }
    }
    const int bbase = (nw * 64 + (lane >> 2)) * ASTR + (lane & 3) * 2;

    float D[2][8][4];
#pragma unroll
    for (int mt = 0; mt < 2; mt++)
#pragma unroll
        for (int j = 0; j < 8; j++)
#pragma unroll
            for (int e = 0; e < 4; e++) D[mt][j][e] = 0.f;

    const int arow  = tid >> 1;
    const int ahalf = tid & 1;
    const bool aok  = (m0 + arow) < MROWS;
    const __half* agh = g_ahi + (size_t)(m0 + arow) * KP + ahalf * 8;
    const __half* agl = g_alo + (size_t)(m0 + arow) * KP + ahalf * 8;
    const __half* wgh = g_whi + (size_t)(n0 + arow) * KP + ahalf * 8;
    const __half* wgl = g_wlo + (size_t)(n0 + arow) * KP + ahalf * 8;
    __half* dah = sah + arow * ASTR + ahalf * 8;
    __half* dal = sal + arow * ASTR + ahalf * 8;
    __half* dwh = swh + arow * ASTR + ahalf * 8;
    __half* dwl = swl + arow * ASTR + ahalf * 8;

    for (int it = 0; it < KP / 16; it++) {
        const int k0 = it * 16;
        if (aok) {
            *(uint4*)dah = *(const uint4*)(agh + k0);
            *(uint4*)dal = *(const uint4*)(agl + k0);
        }
        *(uint4*)dwh = *(const uint4*)(wgh + k0);
        *(uint4*)dwl = *(const uint4*)(wgl + k0);
        __syncthreads();

        uint32_t ah[2][4], al[2][4];
        ldm_x4(ah[0], abh[0]); ldm_x4(ah[1], abh[1]);
        ldm_x4(al[0], abl[0]); ldm_x4(al[1], abl[1]);
#pragma unroll
        for (int j = 0; j < 8; j++) {
            const int bo = bbase + j * 8 * ASTR;
            const uint32_t bh0 = *(const uint32_t*)(swh + bo);
            const uint32_t bh1 = *(const uint32_t*)(swh + bo + 8);
            const uint32_t bl0 = *(const uint32_t*)(swl + bo);
            const uint32_t bl1 = *(const uint32_t*)(swl + bo + 8);
#pragma unroll
            for (int mt = 0; mt < 2; mt++) {
                mma_fp16(D[mt][j], ah[mt], bh0, bh1);
                mma_fp16(D[mt][j], ah[mt], bl0, bl1);
                mma_fp16(D[mt][j], al[mt], bh0, bh1);
            }
        }
        __syncthreads();
    }

    const int rb = m0 + mw * 32 + (lane >> 2);
    const int cb = n0 + nw * 64 + (lane & 3) * 2;
#pragma unroll
    for (int j = 0; j < 8; j++) {
        const int c = cb + j * 8;
        const float b0v = bias[c], b1v = bias[c + 1];
#pragma unroll
        for (int mt = 0; mt < 2; mt++) {
            const int r0 = rb + mt * 16;
            if (r0 < MROWS) {
                g_xg[(size_t)r0 * G3 + c    ] = D[mt][j][0] + b0v;
                g_xg[(size_t)r0 * G3 + c + 1] = D[mt][j][1] + b1v;
            }
            if (r0 + 8 < MROWS) {
                g_xg[(size_t)(r0 + 8) * G3 + c    ] = D[mt][j][2] + b0v;
                g_xg[(size_t)(r0 + 8) * G3 + c + 1] = D[mt][j][3] + b1v;
            }
        }
    }
}

// ---------------- fused two-layer GRU: B-frags in registers -----------------
// 128 blocks; block q owns units [4q,4q+4) of both layers. Weight fragments
// (40 rows incl pad: 0-11 hh0, 12-23 ih1, 24-35 hh1, 36-39 zero) live in
// 160 registers per thread, loaded once. Per step only h is staged to smem.
__global__ __launch_bounds__(256, 1) void gru_fused_kernel(
    const float* __restrict__ w_hh0, const float* __restrict__ b_hh0,
    const float* __restrict__ w_ih1, const float* __restrict__ b_ih1,
    const float* __restrict__ w_hh1, const float* __restrict__ b_hh1,
    const float* __restrict__ hinit)  // [2][25][512]
{
    extern __shared__ __half smh[];
    __half* sh0 = smh;                         // [26][520]
    __half* sh1 = sh0 + HROWS * WSTR;          // [26][520]
    float* ps    = (float*)(sh1 + HROWS * WSTR); // [4][40][33]
    float* bs    = ps + 4 * 40 * 33;           // [36] (+pad)
    float* xring = bs + 64;                    // [4][304] xg cp.async ring

    const int tid  = threadIdx.x;
    const int wid  = tid >> 5;
    const int lane = tid & 31;
    const int u0   = blockIdx.x * 4;
    const int mt   = wid & 1;          // m-tile (batch 0-15 / 16-31)
    const int kw   = wid >> 1;         // k-slice index
    const int kb   = kw * 128;         // k base (fp16 elems)

    const float* hinit0 = hinit;
    const float* hinit1 = hinit + BATCH * HID;

    // ---- prologue: B fragments into registers (fragment-layout global load)
    uint32_t Bh0[5][8], Bh1[5][8], Bl0[5][8], Bl1[5][8];
    {
        const float* mats[3] = { w_hh0, w_ih1, w_hh1 };
        const int rloc = lane >> 2;            // 0..7 (row within n8 tile)
        const int kq   = (lane & 3) << 1;      // 0,2,4,6
#pragma unroll
        for (int nt = 0; nt < 5; nt++) {
            const int j = nt * 8 + rloc;       // 0..39
            const float* wrow = nullptr;
            if (j < 36) {
                const int m = j / 12, r = j % 12;
                wrow = mats[m]
                     + (size_t)((r >> 2) * HID + u0 + (r & 3)) * HID;
            }
#pragma unroll
            for (int ks = 0; ks < 8; ks++) {
                float2 v0 = make_float2(0.f, 0.f);
                float2 v1 = make_float2(0.f, 0.f);
                if (wrow) {
                    const int k = kb + ks * 16 + kq;
                    v0 = *(const float2*)(wrow + k);
                    v1 = *(const float2*)(wrow + k + 8);
                }
                const float h0x = __half2float(__float2half_rn(v0.x));
                const float h0y = __half2float(__float2half_rn(v0.y));
                const float h1x = __half2float(__float2half_rn(v1.x));
                const float h1y = __half2float(__float2half_rn(v1.y));
                Bh0[nt][ks] = pack_h2(v0.x, v0.y);
                Bh1[nt][ks] = pack_h2(v1.x, v1.y);
                Bl0[nt][ks] = pack_h2(v0.x - h0x, v0.y - h0y);
                Bl1[nt][ks] = pack_h2(v1.x - h1x, v1.y - h1y);
            }
        }
    }

    // biases + zero pad row of h staging
    if (tid < 36) {
        const int m = tid / 12, r = tid % 12;
        const float* bp = (m == 0) ? b_hh0 : (m == 1) ? b_ih1 : b_hh1;
        bs[tid] = bp[(r >> 2) * HID + u0 + (r & 3)];
    }
    for (int i = tid; i < WSTR; i += 256) {
        sh0[25 * WSTR + i] = __float2half_rn(0.f);
        sh1[25 * WSTR + i] = __float2half_rn(0.f);
    }

    // gate-thread identities + exact fp32 h_old in registers
    const int gb0 = tid >> 2, gu0 = tid & 3;
    const int tl  = tid - 128;
    const int gb1 = tl >> 2,  gu1 = tl & 3;
    float h0old = 0.f, h1old = 0.f;
    if (tid < 100)               h0old = hinit0[gb0 * HID + u0 + gu0];
    if (tid >= 128 && tid < 228) h1old = hinit1[gb1 * HID + u0 + gu1];
    float stR = 0.f, stZ = 0.f, stN = 0.f;   // gx1 sums carried one step

    // ldmatrix lane addressing (A = h, m16k16 tiles)
    uint32_t lb0, lb1;
    {
        const int t  = lane >> 3;
        const int ir = lane & 7;
        int arow = mt * 16 + (t & 1) * 8 + ir;
        if (arow > 25) arow = 25;                       // zeroed pad row
        const int acol = (t >> 1) * 8;
        const uint32_t aoff = (uint32_t)(arow * WSTR + kb + acol) * 2u;
        lb0 = smem_u32(sh0) + aoff;
        lb1 = smem_u32(sh1) + aoff;
    }

    const int r0 = mt ? 16 : 0;
    const int nr = mt ? 9  : 16;     // rows this warp stages

    __syncthreads();

    // ---- prime cp.async xg ring for steps 0..2
#pragma unroll
    for (int t = 0; t < 3; t++) {
        if (tid < 100) {
            const float* xrow =
                g_xg + ((size_t)gb0 * SEQT + t) * G3 + u0 + gu0;
            uint32_t d = smem_u32(xring + (t & 3) * 304 + tid * 3);
            cp_async4(d,     xrow);
            cp_async4(d + 4, xrow + HID);
            cp_async4(d + 8, xrow + 2 * HID);
            asm volatile("cp.async.commit_group;" ::: "memory");
        }
    }

    for (int s = 0; s <= SEQT + 1; s++) {
        // ---- issue xg prefetch for step s+3; wait for slot s
        float xr0 = 0.f, xz0 = 0.f, xn0 = 0.f;
        if (tid < 100) {
            const int t = s + 3;
            if (t < SEQT) {
                const float* xrow =
                    g_xg + ((size_t)gb0 * SEQT + t) * G3 + u0 + gu0;
                uint32_t d = smem_u32(xring + (t & 3) * 304 + tid * 3);
                cp_async4(d,     xrow);
                cp_async4(d + 4, xrow + HID);
                cp_async4(d + 8, xrow + 2 * HID);
            }
            asm volatile("cp.async.commit_group;" ::: "memory");
            asm volatile("cp.async.wait_group 3;" ::: "memory");
            if (s < SEQT) {
                const float* slot = xring + (s & 3) * 304 + tid * 3;
                xr0 = slot[0]; xz0 = slot[1]; xn0 = slot[2];
            }
        }

        // ---- warp-local staging of h0[s-1], h1[s-3] (fp16)
        if (s == 0) {
            for (int i = lane; i < nr * 32; i += 32) {
                const int r = r0 + (i >> 5), q = i & 31;
                float4 v = __ldcg((const float4*)(hinit0 + r * HID + kb) + q);
                const int o = r * WSTR + kb + q * 4;
                sh0[o + 0] = __float2half_rn(v.x);
                sh0[o + 1] = __float2half_rn(v.y);
                sh0[o + 2] = __float2half_rn(v.z);
                sh0[o + 3] = __float2half_rn(v.w);
            }
        } else {
            const __half* s0 = g_h0[(s - 1) & 1];
            for (int i = lane; i < nr * 16; i += 32) {
                const int r = r0 + (i >> 4), q = i & 15;
                float4 vh = __ldcg((const float4*)(s0 + r * HID + kb) + q);
                *((float4*)(sh0 + r * WSTR + kb) + q) = vh;
            }
        }
        if (s <= 2) {
            for (int i = lane; i < nr * 32; i += 32) {
                const int r = r0 + (i >> 5), q = i & 31;
                float4 v = __ldcg((const float4*)(hinit1 + r * HID + kb) + q);
                const int o = r * WSTR + kb + q * 4;
                sh1[o + 0] = __float2half_rn(v.x);
                sh1[o + 1] = __float2half_rn(v.y);
                sh1[o + 2] = __float2half_rn(v.z);
                sh1[o + 3] = __float2half_rn(v.w);
            }
        } else {
            const __half* s1 = g_h1[(s - 1) & 1];
            for (int i = lane; i < nr * 16; i += 32) {
                const int r = r0 + (i >> 4), q = i & 15;
                float4 vh = __ldcg((const float4*)(s1 + r * HID + kb) + q);
                *((float4*)(sh1 + r * WSTR + kb) + q) = vh;
            }
        }
        __syncwarp();

        // ---- MMA pass: D[m16][n8 x5]; weights from registers
        float D[5][4];
#pragma unroll
        for (int n = 0; n < 5; n++)
#pragma unroll
            for (int e = 0; e < 4; e++) D[n][e] = 0.f;

#pragma unroll
        for (int ks = 0; ks < 8; ks++) {
            uint32_t a0[4], a1[4];
            ldm_x4(a0, lb0 + ks * 32);
            ldm_x4(a1, lb1 + ks * 32);
#pragma unroll
            for (int nt = 0; nt < 5; nt++) {
                const uint32_t* A = (nt < 3) ? a0 : a1;
                mma_fp16(D[nt], A, Bh0[nt][ks], Bh1[nt][ks]);
                mma_fp16(D[nt], A, Bl0[nt][ks], Bl1[nt][ks]);
            }
        }

        // ---- dump D frags to ps[kw][row40][batch33]
        {
            const int c2 = (lane & 3) << 1;
            const int b  = mt * 16 + (lane >> 2);
#pragma unroll
            for (int nt = 0; nt < 5; nt++) {
                const int col = nt * 8 + c2;
                ps[(kw * 40 + col    ) * 33 + b    ] = D[nt][0];
                ps[(kw * 40 + col + 1) * 33 + b    ] = D[nt][1];
                ps[(kw * 40 + col    ) * 33 + b + 8] = D[nt][2];
                ps[(kw * 40 + col + 1) * 33 + b + 8] = D[nt][3];
            }
        }
        __syncthreads();

        // ---- layer-0 gates: t = s (threads 0..99)
        if (tid < 100 && s < SEQT) {
            const int u = u0 + gu0;
            float gr_ = bs[gu0], gz_ = bs[4 + gu0], gn_ = bs[8 + gu0];
#pragma unroll
            for (int k = 0; k < 4; k++) {
                gr_ += ps[(k * 40 +     gu0) * 33 + gb0];
                gz_ += ps[(k * 40 + 4 + gu0) * 33 + gb0];
                gn_ += ps[(k * 40 + 8 + gu0) * 33 + gb0];
            }
            const float r = fast_sig(xr0 + gr_);
            const float z = fast_sig(xz0 + gz_);
            const float n = fast_tanh(xn0 + r * gn_);
            const float hn = (1.f - z) * n + z * h0old;
            h0old = hn;
            g_h0[s & 1][gb0 * HID + u] = __float2half_rn(hn);
            if (s == SEQT - 1) g_h0f[gb0 * HID + u] = hn;
        }

        // ---- layer-1 gates: t = s-2 (threads 128..227); stash gx1 for s+1
        if (tid >= 128 && tid < 228) {
            const int u = u0 + gu1;
            float nR = 0.f, nZ = 0.f, nN = 0.f;
            float hr = bs[24 + gu1], hz = bs[28 + gu1], hn_ = bs[32 + gu1];
#pragma unroll
            for (int k = 0; k < 4; k++) {
                nR  += ps[(k * 40 + 12 + gu1) * 33 + gb1];
                nZ  += ps[(k * 40 + 16 + gu1) * 33 + gb1];
                nN  += ps[(k * 40 + 20 + gu1) * 33 + gb1];
                hr  += ps[(k * 40 + 24 + gu1) * 33 + gb1];
                hz  += ps[(k * 40 + 28 + gu1) * 33 + gb1];
                hn_ += ps[(k * 40 + 32 + gu1) * 33 + gb1];
            }
            if (s >= 2) {
                const float xr = bs[12 + gu1] + stR;
                const float xz = bs[16 + gu1] + stZ;
                const float xn = bs[20 + gu1] + stN;
                const float r = fast_sig(xr + hr);
                const float z = fast_sig(xz + hz);
                const float n = fast_tanh(xn + r * hn_);
                const float hnew = (1.f - z) * n + z * h1old;
                h1old = hnew;
                g_h1[s & 1][gb1 * HID + u] = __float2half_rn(hnew);
                if (s == SEQT + 1) g_h1f[gb1 * HID + u] = hnew;
            }
            stR = nR; stZ = nZ; stN = nN;
        }
        __syncthreads();   // h stores + ps reads done before arrive

        // ---- grid barrier: arrive (tid0), per-warp relaxed poll
        if (s < SEQT + 1) {
            if (tid == 0) red_release_add(&g_ctr, 1u);
            const unsigned target = (unsigned)(s + 1) * 128u;
            if (lane == 0) {
                while (ld_relaxed(&g_ctr) < target) { }
            }
            __syncwarp();
        }
    }

    // ---- self-reset: last block to finish zeroes the counters -------------
    if (tid == 0) {
        const unsigned old = atomicAdd(&g_done, 1u);
        if (old == 127u) {
            atomicExch(&g_ctr, 0u);
            atomicExch(&g_done, 0u);
        }
    }
}

// ---------------- finalize: sig = sigmoid(h1_final . fc_w + fc_b); pack out --
__global__ void finalize_kernel(const float* __restrict__ fc_w,
                                const float* __restrict__ fc_b,
                                float* __restrict__ out)
{
    if (blockIdx.x < 100) {
        const int idx = blockIdx.x * 256 + threadIdx.x;     // 0..25599
        const float v = (idx < BATCH * HID) ? g_h0f[idx]
                                            : g_h1f[idx - BATCH * HID];
        out[25 + idx] = v;
    } else {
        const int b = threadIdx.x;
        if (b < BATCH) {
            float s = fc_b[0];
            for (int k = 0; k < HID; k++)
                s += g_h1f[b * HID + k] * fc_w[k];
            out[b] = 1.f / (1.f + expf(-s));
        }
    }
}

// ---------------- launch ----------------------------------------------------
extern "C" void kernel_launch(void* const* d_in, const int* in_sizes, int n_in,
                              void* d_out, int out_size)
{
    const int*   words  = (const int*)  d_in[0];
    const float* hidden = (const float*)d_in[1];
    const float* emb    = (const float*)d_in[2];
    const float* w_ih0  = (const float*)d_in[3];
    const float* w_hh0  = (const float*)d_in[4];
    const float* b_ih0  = (const float*)d_in[5];
    const float* b_hh0  = (const float*)d_in[6];
    const float* w_ih1  = (const float*)d_in[7];
    const float* w_hh1  = (const float*)d_in[8];
    const float* b_ih1  = (const float*)d_in[9];
    const float* b_hh1  = (const float*)d_in[10];
    const float* fc_w   = (const float*)d_in[11];
    const float* fc_b   = (const float*)d_in[12];
    float* out = (float*)d_out;

    const size_t smem_bytes =
        (size_t)(2 * HROWS * WSTR) * sizeof(__half)
        + (size_t)(4 * 40 * 33 + 64 + 4 * 304 + 16) * sizeof(float);
    cudaFuncSetAttribute(gru_fused_kernel,
                         cudaFuncAttributeMaxDynamicSharedMemorySize,
                         (int)smem_bytes);

    // 5-launch pattern; capture idx 3 = gru_fused_kernel
    cvtA_kernel<<<MROWS, KP>>>(words, emb);                          // 0
    cvtW_kernel<<<G3, KP>>>(w_ih0);                                  // 1
    gemm_tc_kernel<<<dim3(G3 / 128, (MROWS + 127) / 128), 256>>>(    // 2
        b_ih0);
    gru_fused_kernel<<<128, 256, smem_bytes>>>(                      // 3
        w_hh0, b_hh0, w_ih1, b_ih1, w_hh1, b_hh1, hidden);
    finalize_kernel<<<101, 256>>>(fc_w, fc_b, out);                  // 4
}